// round 1
// baseline (speedup 1.0000x reference)
#include <cuda_runtime.h>
#include <math.h>

#define B_    8
#define T_    2048
#define NB_   22
#define D_    128
#define O_    128      // WIDTH*2
#define FREQ_ 1025
#define NFFT  2048
#define N2    1024
#define HOP_  512
#define OUTL  1048064  // HOP*(T-1)

// Scratch (static device globals; no runtime allocation)
__device__ float g_band[(size_t)B_ * T_ * NB_ * O_];    // band outputs incl. bias
__device__ float g_frames[(size_t)B_ * T_ * NFFT];      // windowed istft frames

// ---------------------------------------------------------------------------
// K1: band GEMM.  band[b,t,n,o] = sum_d z[b,t,n,d] * W[n,d,o] + bias[n,o]
// Block: (t-tile of 64) x (band n) x (batch b). 256 threads, 4x8 register tile.
// ---------------------------------------------------------------------------
__global__ __launch_bounds__(256) void k_gemm(const float* __restrict__ z,
                                              const float* __restrict__ W,
                                              const float* __restrict__ bias)
{
    extern __shared__ float sm[];
    float* Ws = sm;                  // 128*128
    float* Zs = sm + 16384;          // 64 rows * 132 (padded)
    float* bs = sm + 16384 + 64 * 132;  // 128

    const int n  = blockIdx.y;
    const int b  = blockIdx.z;
    const int t0 = blockIdx.x * 64;
    const int tid = threadIdx.x;

    // Load W[n] (16384 floats) via float4
    {
        const float4* Wg = (const float4*)(W + (size_t)n * 128 * 128);
        float4* Ws4 = (float4*)Ws;
#pragma unroll
        for (int i = 0; i < 16; i++) Ws4[tid + 256 * i] = Wg[tid + 256 * i];
    }
    if (tid < 128) bs[tid] = bias[n * 128 + tid];

    // Load z tile: 64 rows x 128 (as 32 float4/row)
#pragma unroll
    for (int i = 0; i < 8; i++) {
        int e = tid + 256 * i;           // 0..2047
        int r = e >> 5;
        int c = e & 31;
        float4 v = *(const float4*)(z + (((size_t)(b * T_ + t0 + r)) * NB_ + n) * 128 + c * 4);
        *(float4*)&Zs[r * 132 + c * 4] = v;
    }
    __syncthreads();

    const int tx = tid & 15;    // o-group: o = tx*8 .. tx*8+7
    const int ty = tid >> 4;    // t-group: t = t0 + ty*4 .. +3

    float acc[4][8];
#pragma unroll
    for (int i = 0; i < 4; i++)
#pragma unroll
        for (int j = 0; j < 8; j++) acc[i][j] = 0.0f;

#pragma unroll 4
    for (int k = 0; k < 128; k++) {
        float4 w0 = *(float4*)&Ws[k * 128 + tx * 8];
        float4 w1 = *(float4*)&Ws[k * 128 + tx * 8 + 4];
        float wv[8] = {w0.x, w0.y, w0.z, w0.w, w1.x, w1.y, w1.z, w1.w};
        float av[4];
#pragma unroll
        for (int i = 0; i < 4; i++) av[i] = Zs[(ty * 4 + i) * 132 + k];
#pragma unroll
        for (int i = 0; i < 4; i++)
#pragma unroll
            for (int j = 0; j < 8; j++) acc[i][j] = fmaf(av[i], wv[j], acc[i][j]);
    }

#pragma unroll
    for (int i = 0; i < 4; i++) {
        int t = t0 + ty * 4 + i;
        float* outp = g_band + (((size_t)(b * T_ + t)) * NB_ + n) * 128 + tx * 8;
#pragma unroll
        for (int j = 0; j < 8; j++) outp[j] = acc[i][j] + bs[tx * 8 + j];
    }
}

// ---------------------------------------------------------------------------
// K2: per-frame mask gather + complex multiply + irfft(2048) + Hann window.
// One block per (b,t) frame; 256 threads. irfft via hermitian pack into a
// 1024-pt complex inverse Stockham radix-4 FFT (5 stages, smem ping-pong).
// ---------------------------------------------------------------------------
__device__ __forceinline__ float2 cmul(float2 a, float2 b) {
    return make_float2(a.x * b.x - a.y * b.y, a.x * b.y + a.y * b.x);
}

__global__ __launch_bounds__(256) void k_fft(const float* __restrict__ mix)
{
    __shared__ float  bandv[NB_ * O_];    // 2816 floats
    __shared__ float2 X[FREQ_];           // masked spectrum
    __shared__ float2 bufA[N2];
    __shared__ float2 bufB[N2];

    const int frame = blockIdx.x;         // b*T_ + t
    const int b = frame >> 11;
    const int t = frame & 2047;
    const int tid = threadIdx.x;

    // Load band outputs for this frame
    {
        const float* bf = g_band + (size_t)frame * (NB_ * O_);
        for (int i = tid; i < NB_ * O_; i += 256) bandv[i] = bf[i];
    }
    __syncthreads();

    // Build X[f] = mask[f] * mix[f] (complex)
    const float* mr = mix + ((size_t)(b * 2 + 0) * T_ + t) * FREQ_;
    const float* mi = mix + ((size_t)(b * 2 + 1) * T_ + t) * FREQ_;
    for (int f = tid; f < FREQ_; f += 256) {
        float sr = 0.0f, si = 0.0f;
        int cnt = 0;
        int n1 = f / 48; if (n1 > 20) n1 = 20;
        int n0 = (f >= 63) ? (f - 63 + 47) / 48 : 0;
        for (int n = n0; n <= n1; n++) {
            int col = f - 48 * n;
            sr += bandv[n * 128 + 2 * col];
            si += bandv[n * 128 + 2 * col + 1];
            cnt++;
        }
        if (f >= 961) {
            int col = f - 961;
            sr += bandv[21 * 128 + 2 * col];
            si += bandv[21 * 128 + 2 * col + 1];
            cnt++;
        }
        float invw = 1.0f / (float)(cnt > 0 ? cnt : 1);
        float maskr = sr * invw, maski = si * invw;
        float xr = mr[f], xi = mi[f];
        X[f] = make_float2(maskr * xr - maski * xi, maskr * xi + maski * xr);
    }
    __syncthreads();

    // Hermitian pack: Zf[j] = (X[j]+conj(X[1024-j])) + i*e^{i*pi*j/1024}*(X[j]-conj(X[1024-j]))
    // (imag of DC and Nyquist discarded, matching pocketfft/cuFFT C2R)
    for (int j = tid; j < N2; j += 256) {
        float2 zv;
        if (j == 0) {
            float x0 = X[0].x, xn = X[1024].x;
            zv = make_float2(x0 + xn, x0 - xn);
        } else {
            float2 u = X[j];
            float2 v = X[1024 - j];
            float Ar = u.x + v.x, Ai = u.y - v.y;
            float Dr = u.x - v.x, Di = u.y + v.y;
            float s, c;
            sincospif((float)j * (1.0f / 1024.0f), &s, &c);
            zv = make_float2(Ar - s * Dr - c * Di, Ai + c * Dr - s * Di);
        }
        bufA[j] = zv;
    }
    __syncthreads();

    // 5 radix-4 Stockham stages, inverse (e^{+i}), natural in / natural out
    float2* src = bufA;
    float2* dst = bufB;
#pragma unroll
    for (int stage = 0; stage < 5; stage++) {
        const int shift = 2 * stage;
        const int ns = 1 << shift;
        const int j = tid;                 // N2/4 == blockDim
        const int base = j & (ns - 1);

        float2 a  = src[j];
        float2 bb = src[j + 256];
        float2 cc = src[j + 512];
        float2 dd = src[j + 768];

        // twiddles: w_q = exp(+i * q * pi * base/(2*ns))
        float s1, c1;
        sincospif((float)base / (float)(2 * ns), &s1, &c1);
        float2 w1 = make_float2(c1, s1);
        float2 w2 = cmul(w1, w1);
        float2 w3 = cmul(w2, w1);
        bb = cmul(bb, w1);
        cc = cmul(cc, w2);
        dd = cmul(dd, w3);

        float2 p = make_float2(a.x + cc.x, a.y + cc.y);
        float2 m = make_float2(a.x - cc.x, a.y - cc.y);
        float2 q = make_float2(bb.x + dd.x, bb.y + dd.y);
        float2 r = make_float2(bb.x - dd.x, bb.y - dd.y);
        float2 ir = make_float2(-r.y, r.x);   // i * r

        int idx = ((j >> shift) << (shift + 2)) + base;
        dst[idx]          = make_float2(p.x + q.x, p.y + q.y);   // Y0
        dst[idx + ns]     = make_float2(m.x + ir.x, m.y + ir.y); // Y1
        dst[idx + 2 * ns] = make_float2(p.x - q.x, p.y - q.y);   // Y2
        dst[idx + 3 * ns] = make_float2(m.x - ir.x, m.y - ir.y); // Y3
        __syncthreads();
        float2* tmp = src; src = dst; dst = tmp;
    }
    // result now in `src` (after final swap)

    // unpack to 2048 real samples, apply Hann window, 1/2048 irfft scale
    const float invN = 1.0f / 2048.0f;
    float* fout = g_frames + (size_t)frame * NFFT;
#pragma unroll
    for (int rix = 0; rix < 8; rix++) {
        int i = tid + 256 * rix;
        float2 zm = src[i >> 1];
        float v = (i & 1) ? zm.y : zm.x;
        float wv = 0.5f - 0.5f * cospif((float)i * (1.0f / 1024.0f));
        fout[i] = v * invN * wv;
    }
}

// ---------------------------------------------------------------------------
// K3: overlap-add gather + envelope normalize + crop.
// out[b][s] = sum_t frames[b][t][p-512t] / env(p),  p = s + 1024
// ---------------------------------------------------------------------------
__global__ __launch_bounds__(256) void k_ola(float* __restrict__ out)
{
    const int b = blockIdx.y;
    const int s = blockIdx.x * 256 + threadIdx.x;   // 0..OUTL-1 (grid exact)
    const int p = s + 1024;

    int thi = p >> 9;
    if (thi > T_ - 1) thi = T_ - 1;
    int tlo = (p >= NFFT) ? ((p - (NFFT - 1) + (HOP_ - 1)) >> 9) : 0;

    float acc = 0.0f, env = 0.0f;
    for (int t = tlo; t <= thi; t++) {
        int off = p - (t << 9);
        acc += g_frames[((size_t)(b * T_ + t)) * NFFT + off];
        float w = 0.5f - 0.5f * cospif((float)off * (1.0f / 1024.0f));
        env = fmaf(w, w, env);
    }
    out[(size_t)b * OUTL + s] = acc / (env > 1e-11f ? env : 1.0f);
}

// ---------------------------------------------------------------------------
extern "C" void kernel_launch(void* const* d_in, const int* in_sizes, int n_in,
                              void* d_out, int out_size)
{
    const float* z    = (const float*)d_in[0];
    const float* mix  = (const float*)d_in[1];
    const float* W    = (const float*)d_in[2];
    const float* bias = (const float*)d_in[3];
    float* out = (float*)d_out;

    const int smem_gemm = (16384 + 64 * 132 + 128) * 4;   // 99840 B
    cudaFuncSetAttribute(k_gemm, cudaFuncAttributeMaxDynamicSharedMemorySize, smem_gemm);

    k_gemm<<<dim3(T_ / 64, NB_, B_), 256, smem_gemm>>>(z, W, bias);
    k_fft<<<B_ * T_, 256>>>(mix);
    k_ola<<<dim3(OUTL / 256, B_), 256>>>(out);
}

// round 5
// speedup vs baseline: 1.8653x; 1.8653x over previous
#include <cuda_runtime.h>
#include <cuda_bf16.h>
#include <cstdint>
#include <math.h>

#define B_    8
#define T_    2048
#define NB_   22
#define D_    128
#define O_    128      // WIDTH*2
#define FREQ_ 1025
#define NFFT  2048
#define N2    1024
#define HOP_  512
#define OUTL  1048064  // HOP*(T-1)

// Scratch (static device globals; no runtime allocation)
__device__ float g_band[(size_t)B_ * T_ * NB_ * O_];    // band outputs incl. bias
__device__ float g_frames[(size_t)B_ * T_ * NFFT];      // windowed istft frames

// Precomputed tables (filled by k_init every launch; deterministic)
__device__ float2 g_tw[5][256];   // FFT stage twiddles w1
__device__ float2 g_pk[1024];     // hermitian pack twiddles (cos, sin) of pi*j/1024
__device__ float  g_win[2048];    // hann window
__device__ float  g_win2[2048];   // hann^2

// ---------------------------------------------------------------------------
// K0: fill twiddle/window tables (cheap, graph-capturable, deterministic)
// ---------------------------------------------------------------------------
__global__ void k_init()
{
    int i = blockIdx.x * 256 + threadIdx.x;   // 0..2047
    if (i < 2048) {
        float w = 0.5f - 0.5f * cospif((float)i * (1.0f / 1024.0f));
        g_win[i] = w;
        g_win2[i] = w * w;
    }
    if (i < 1024) {
        float s, c;
        sincospif((float)i * (1.0f / 1024.0f), &s, &c);
        g_pk[i] = make_float2(c, s);
    }
    if (i < 256) {
#pragma unroll
        for (int st = 0; st < 5; st++) {
            int ns = 1 << (2 * st);
            int base = i & (ns - 1);
            float s, c;
            sincospif((float)base / (float)(2 * ns), &s, &c);
            g_tw[st][i] = make_float2(c, s);
        }
    }
}

// ---------------------------------------------------------------------------
// K1: band GEMM via bf16 mma.sync (m16n8k16).
// band[b,t,n,o] = sum_d z[b,t,n,d] * W[n,d,o] + bias[n,o]
// Block: 128 t-rows x 128 o, one band n, one batch b. 256 threads (8 warps),
// each warp computes a 16x128 strip. fp32 accumulate, fp32 bias epilogue.
// ---------------------------------------------------------------------------
#define ZSTR 136   // padded bf16 row stride

__global__ __launch_bounds__(256) void k_gemm(const float* __restrict__ z,
                                              const float* __restrict__ W,
                                              const float* __restrict__ bias)
{
    extern __shared__ char smraw[];
    __nv_bfloat16* Za = (__nv_bfloat16*)smraw;            // [128][ZSTR]
    __nv_bfloat16* Wt = Za + 128 * ZSTR;                  // [128][ZSTR]  (o-major: Wt[o][d])
    float* bs = (float*)(Wt + 128 * ZSTR);                // [128]

    const int n  = blockIdx.y;
    const int b  = blockIdx.z;
    const int t0 = blockIdx.x * 128;
    const int tid = threadIdx.x;

    // Load z tile 128x128 fp32 -> bf16 smem (row-major)
#pragma unroll
    for (int i = 0; i < 16; i++) {
        int idx = tid + 256 * i;          // 0..4095 float4s
        int r = idx >> 5;
        int c4 = idx & 31;
        float4 v = *(const float4*)(z + (((size_t)(b * T_ + t0 + r)) * NB_ + n) * 128 + c4 * 4);
        __nv_bfloat162* dst = (__nv_bfloat162*)&Za[r * ZSTR + c4 * 4];
        dst[0] = __float22bfloat162_rn(make_float2(v.x, v.y));
        dst[1] = __float22bfloat162_rn(make_float2(v.z, v.w));
    }

    // Load W[n] 128x128 fp32, transpose into Wt[o][d] bf16
#pragma unroll
    for (int i = 0; i < 64; i++) {
        int idx = tid + 256 * i;          // 0..16383
        int d = idx >> 7;
        int o = idx & 127;
        float v = W[(size_t)n * 16384 + idx];
        Wt[o * ZSTR + d] = __float2bfloat16(v);
    }
    if (tid < 128) bs[tid] = bias[n * 128 + tid];
    __syncthreads();

    const int w    = tid >> 5;
    const int lane = tid & 31;
    const int gr   = lane >> 2;         // 0..7
    const int qc   = (lane & 3) * 2;    // 0,2,4,6
    const int r0   = w * 16;

    float acc[16][4];
#pragma unroll
    for (int nt = 0; nt < 16; nt++)
#pragma unroll
        for (int j = 0; j < 4; j++) acc[nt][j] = 0.0f;

    for (int ks = 0; ks < 8; ks++) {
        const int k0 = ks * 16;
        uint32_t a0 = *(const uint32_t*)&Za[(r0 + gr) * ZSTR + k0 + qc];
        uint32_t a1 = *(const uint32_t*)&Za[(r0 + gr + 8) * ZSTR + k0 + qc];
        uint32_t a2 = *(const uint32_t*)&Za[(r0 + gr) * ZSTR + k0 + qc + 8];
        uint32_t a3 = *(const uint32_t*)&Za[(r0 + gr + 8) * ZSTR + k0 + qc + 8];
#pragma unroll
        for (int nt = 0; nt < 16; nt++) {
            const int n0 = nt * 8;
            uint32_t b0 = *(const uint32_t*)&Wt[(n0 + gr) * ZSTR + k0 + qc];
            uint32_t b1 = *(const uint32_t*)&Wt[(n0 + gr) * ZSTR + k0 + qc + 8];
            asm volatile(
                "mma.sync.aligned.m16n8k16.row.col.f32.bf16.bf16.f32 "
                "{%0,%1,%2,%3}, {%4,%5,%6,%7}, {%8,%9}, {%0,%1,%2,%3};\n"
                : "+f"(acc[nt][0]), "+f"(acc[nt][1]), "+f"(acc[nt][2]), "+f"(acc[nt][3])
                : "r"(a0), "r"(a1), "r"(a2), "r"(a3), "r"(b0), "r"(b1));
        }
    }

    // Epilogue: add bias (fp32), write to g_band
    const int row0 = t0 + r0 + gr;
    const int row1 = row0 + 8;
#pragma unroll
    for (int nt = 0; nt < 16; nt++) {
        const int col = nt * 8 + qc;
        float bsc0 = bs[col], bsc1 = bs[col + 1];
        float* p0 = g_band + (((size_t)(b * T_ + row0)) * NB_ + n) * 128 + col;
        float* p1 = g_band + (((size_t)(b * T_ + row1)) * NB_ + n) * 128 + col;
        *(float2*)p0 = make_float2(acc[nt][0] + bsc0, acc[nt][1] + bsc1);
        *(float2*)p1 = make_float2(acc[nt][2] + bsc0, acc[nt][3] + bsc1);
    }
}

// ---------------------------------------------------------------------------
// K2: per-frame mask gather + complex multiply + irfft(2048) + Hann window.
// One block per (b,t) frame; 256 threads. irfft via hermitian pack into a
// 1024-pt complex inverse Stockham radix-4 FFT (5 stages, smem ping-pong).
// ---------------------------------------------------------------------------
__device__ __forceinline__ float2 cmul(float2 a, float2 b) {
    return make_float2(a.x * b.x - a.y * b.y, a.x * b.y + a.y * b.x);
}

__global__ __launch_bounds__(256) void k_fft(const float* __restrict__ mix)
{
    __shared__ float  bandv[NB_ * O_];    // 2816 floats
    __shared__ float2 X[FREQ_];           // masked spectrum
    __shared__ float2 bufA[N2];
    __shared__ float2 bufB[N2];

    const int frame = blockIdx.x;         // b*T_ + t
    const int b = frame >> 11;
    const int t = frame & 2047;
    const int tid = threadIdx.x;

    // Load band outputs for this frame
    {
        const float* bf = g_band + (size_t)frame * (NB_ * O_);
        for (int i = tid; i < NB_ * O_; i += 256) bandv[i] = bf[i];
    }
    __syncthreads();

    // Build X[f] = mask[f] * mix[f] (complex)
    const float* mr = mix + ((size_t)(b * 2 + 0) * T_ + t) * FREQ_;
    const float* mi = mix + ((size_t)(b * 2 + 1) * T_ + t) * FREQ_;
    for (int f = tid; f < FREQ_; f += 256) {
        float sr = 0.0f, si = 0.0f;
        int cnt = 0;
        int n1 = f / 48; if (n1 > 20) n1 = 20;
        int n0 = (f >= 63) ? (f - 63 + 47) / 48 : 0;
        for (int nn = n0; nn <= n1; nn++) {
            int col = f - 48 * nn;
            sr += bandv[nn * 128 + 2 * col];
            si += bandv[nn * 128 + 2 * col + 1];
            cnt++;
        }
        if (f >= 961) {
            int col = f - 961;
            sr += bandv[21 * 128 + 2 * col];
            si += bandv[21 * 128 + 2 * col + 1];
            cnt++;
        }
        float invw = 1.0f / (float)(cnt > 0 ? cnt : 1);
        float maskr = sr * invw, maski = si * invw;
        float xr = mr[f], xi = mi[f];
        X[f] = make_float2(maskr * xr - maski * xi, maskr * xi + maski * xr);
    }
    __syncthreads();

    // Hermitian pack (imag of DC/Nyquist discarded, matching C2R semantics)
    for (int j = tid; j < N2; j += 256) {
        float2 zv;
        if (j == 0) {
            float x0 = X[0].x, xn = X[1024].x;
            zv = make_float2(x0 + xn, x0 - xn);
        } else {
            float2 u = X[j];
            float2 v = X[1024 - j];
            float Ar = u.x + v.x, Ai = u.y - v.y;
            float Dr = u.x - v.x, Di = u.y + v.y;
            float2 cs = g_pk[j];            // (cos, sin)
            float c = cs.x, s = cs.y;
            zv = make_float2(Ar - s * Dr - c * Di, Ai + c * Dr - s * Di);
        }
        bufA[j] = zv;
    }
    __syncthreads();

    // 5 radix-4 Stockham stages, inverse (e^{+i}), natural in / natural out
    float2* src = bufA;
    float2* dst = bufB;
#pragma unroll
    for (int stage = 0; stage < 5; stage++) {
        const int shift = 2 * stage;
        const int ns = 1 << shift;
        const int j = tid;                 // N2/4 == blockDim
        const int base = j & (ns - 1);

        float2 a  = src[j];
        float2 bb = src[j + 256];
        float2 cc = src[j + 512];
        float2 dd = src[j + 768];

        float2 w1 = g_tw[stage][j];        // exp(+i*pi*base/(2ns))
        float2 w2 = cmul(w1, w1);
        float2 w3 = cmul(w2, w1);
        bb = cmul(bb, w1);
        cc = cmul(cc, w2);
        dd = cmul(dd, w3);

        float2 p = make_float2(a.x + cc.x, a.y + cc.y);
        float2 m = make_float2(a.x - cc.x, a.y - cc.y);
        float2 q = make_float2(bb.x + dd.x, bb.y + dd.y);
        float2 r = make_float2(bb.x - dd.x, bb.y - dd.y);
        float2 ir = make_float2(-r.y, r.x);   // i * r

        int idx = ((j >> shift) << (shift + 2)) + base;
        dst[idx]          = make_float2(p.x + q.x, p.y + q.y);   // Y0
        dst[idx + ns]     = make_float2(m.x + ir.x, m.y + ir.y); // Y1
        dst[idx + 2 * ns] = make_float2(p.x - q.x, p.y - q.y);   // Y2
        dst[idx + 3 * ns] = make_float2(m.x - ir.x, m.y - ir.y); // Y3
        __syncthreads();
        float2* tmp = src; src = dst; dst = tmp;
    }

    // unpack to 2048 real samples, apply Hann window, 1/2048 irfft scale
    const float invN = 1.0f / 2048.0f;
    float* fout = g_frames + (size_t)frame * NFFT;
#pragma unroll
    for (int rix = 0; rix < 8; rix++) {
        int i = tid + 256 * rix;
        float2 zm = src[i >> 1];
        float v = (i & 1) ? zm.y : zm.x;
        fout[i] = v * invN * g_win[i];
    }
}

// ---------------------------------------------------------------------------
// K3: overlap-add gather + envelope normalize + crop.
// out[b][s] = sum_t frames[b][t][p-512t] / env(p),  p = s + 1024
// ---------------------------------------------------------------------------
__global__ __launch_bounds__(256) void k_ola(float* __restrict__ out)
{
    const int b = blockIdx.y;
    const int s = blockIdx.x * 256 + threadIdx.x;   // 0..OUTL-1 (grid exact)
    const int p = s + 1024;

    int thi = p >> 9;
    if (thi > T_ - 1) thi = T_ - 1;
    int tlo = (p >= NFFT) ? ((p - (NFFT - 1) + (HOP_ - 1)) >> 9) : 0;

    float acc = 0.0f, env = 0.0f;
    for (int t = tlo; t <= thi; t++) {
        int off = p - (t << 9);
        acc += g_frames[((size_t)(b * T_ + t)) * NFFT + off];
        env += g_win2[off];
    }
    out[(size_t)b * OUTL + s] = acc / (env > 1e-11f ? env : 1.0f);
}

// ---------------------------------------------------------------------------
extern "C" void kernel_launch(void* const* d_in, const int* in_sizes, int n_in,
                              void* d_out, int out_size)
{
    const float* z    = (const float*)d_in[0];
    const float* mix  = (const float*)d_in[1];
    const float* W    = (const float*)d_in[2];
    const float* bias = (const float*)d_in[3];
    float* out = (float*)d_out;

    const int smem_gemm = (128 * ZSTR * 2) * 2 + 128 * 4;   // Za + Wt (bf16) + bias
    cudaFuncSetAttribute(k_gemm, cudaFuncAttributeMaxDynamicSharedMemorySize, smem_gemm);

    k_init<<<8, 256>>>();
    k_gemm<<<dim3(T_ / 128, NB_, B_), 256, smem_gemm>>>(z, W, bias);
    k_fft<<<B_ * T_, 256>>>(mix);
    k_ola<<<dim3(OUTL / 256, B_), 256>>>(out);
}

// round 6
// speedup vs baseline: 2.2052x; 1.1822x over previous
#include <cuda_runtime.h>
#include <cuda_bf16.h>
#include <cstdint>
#include <math.h>

#define B_    8
#define T_    2048
#define NB_   22
#define D_    128
#define O_    128      // WIDTH*2
#define FREQ_ 1025
#define NFFT  2048
#define N2    1024
#define HOP_  512
#define OUTL  1048064  // HOP*(T-1)

// Scratch (static device globals; no runtime allocation)
__device__ __nv_bfloat16 g_band[(size_t)B_ * T_ * NB_ * O_];  // band residual (no bias), bf16
__device__ float g_frames[(size_t)B_ * T_ * NFFT];            // windowed istft frames

// Precomputed tables (filled by k_init every launch; deterministic)
__device__ float2 g_tw[5][256];   // FFT stage twiddles w1
__device__ float2 g_pk[1024];     // hermitian pack twiddles (cos, sin) of pi*j/1024
__device__ float  g_win[2048];    // hann window
__device__ float  g_win2[2048];   // hann^2
__device__ float4 g_mb[FREQ_];    // (bias_r*invw, bias_i*invw, invw, 0) per freq

// ---------------------------------------------------------------------------
// K0: fill twiddle/window/mask-bias tables (graph-capturable, deterministic)
// ---------------------------------------------------------------------------
__global__ void k_init(const float* __restrict__ bias)
{
    int i = blockIdx.x * 256 + threadIdx.x;   // 0..2047
    if (i < 2048) {
        float w = 0.5f - 0.5f * cospif((float)i * (1.0f / 1024.0f));
        g_win[i] = w;
        g_win2[i] = w * w;
    }
    if (i < 1024) {
        float s, c;
        sincospif((float)i * (1.0f / 1024.0f), &s, &c);
        g_pk[i] = make_float2(c, s);
    }
    if (i < 256) {
#pragma unroll
        for (int st = 0; st < 5; st++) {
            int ns = 1 << (2 * st);
            int base = i & (ns - 1);
            float s, c;
            sincospif((float)base / (float)(2 * ns), &s, &c);
            g_tw[st][i] = make_float2(c, s);
        }
    }
    if (i < FREQ_) {
        int f = i;
        float br = 0.0f, bi = 0.0f;
        int cnt = 0;
        int n1 = f / 48; if (n1 > 20) n1 = 20;
        int n0 = (f >= 63) ? (f - 63 + 47) / 48 : 0;
        for (int nn = n0; nn <= n1; nn++) {
            int col = f - 48 * nn;
            br += bias[nn * 128 + 2 * col];
            bi += bias[nn * 128 + 2 * col + 1];
            cnt++;
        }
        if (f >= 961) {
            int col = f - 961;
            br += bias[21 * 128 + 2 * col];
            bi += bias[21 * 128 + 2 * col + 1];
            cnt++;
        }
        float invw = 1.0f / (float)(cnt > 0 ? cnt : 1);
        g_mb[f] = make_float4(br * invw, bi * invw, invw, 0.0f);
    }
}

// ---------------------------------------------------------------------------
// K1: band GEMM via bf16 mma.sync (m16n8k16). Writes bf16 RESIDUAL (no bias).
// ---------------------------------------------------------------------------
#define ZSTR 136   // padded bf16 row stride

__global__ __launch_bounds__(256) void k_gemm(const float* __restrict__ z,
                                              const float* __restrict__ W)
{
    extern __shared__ char smraw[];
    __nv_bfloat16* Za = (__nv_bfloat16*)smraw;            // [128][ZSTR]
    __nv_bfloat16* Wt = Za + 128 * ZSTR;                  // [128][ZSTR]  (o-major: Wt[o][d])

    const int n  = blockIdx.y;
    const int b  = blockIdx.z;
    const int t0 = blockIdx.x * 128;
    const int tid = threadIdx.x;

    // Load z tile 128x128 fp32 -> bf16 smem (row-major)
#pragma unroll
    for (int i = 0; i < 16; i++) {
        int idx = tid + 256 * i;          // 0..4095 float4s
        int r = idx >> 5;
        int c4 = idx & 31;
        float4 v = *(const float4*)(z + (((size_t)(b * T_ + t0 + r)) * NB_ + n) * 128 + c4 * 4);
        __nv_bfloat162* dst = (__nv_bfloat162*)&Za[r * ZSTR + c4 * 4];
        dst[0] = __float22bfloat162_rn(make_float2(v.x, v.y));
        dst[1] = __float22bfloat162_rn(make_float2(v.z, v.w));
    }

    // Load W[n] 128x128 fp32, transpose into Wt[o][d] bf16
#pragma unroll
    for (int i = 0; i < 64; i++) {
        int idx = tid + 256 * i;          // 0..16383
        int d = idx >> 7;
        int o = idx & 127;
        float v = W[(size_t)n * 16384 + idx];
        Wt[o * ZSTR + d] = __float2bfloat16(v);
    }
    __syncthreads();

    const int w    = tid >> 5;
    const int lane = tid & 31;
    const int gr   = lane >> 2;         // 0..7
    const int qc   = (lane & 3) * 2;    // 0,2,4,6
    const int r0   = w * 16;

    float acc[16][4];
#pragma unroll
    for (int nt = 0; nt < 16; nt++)
#pragma unroll
        for (int j = 0; j < 4; j++) acc[nt][j] = 0.0f;

    for (int ks = 0; ks < 8; ks++) {
        const int k0 = ks * 16;
        uint32_t a0 = *(const uint32_t*)&Za[(r0 + gr) * ZSTR + k0 + qc];
        uint32_t a1 = *(const uint32_t*)&Za[(r0 + gr + 8) * ZSTR + k0 + qc];
        uint32_t a2 = *(const uint32_t*)&Za[(r0 + gr) * ZSTR + k0 + qc + 8];
        uint32_t a3 = *(const uint32_t*)&Za[(r0 + gr + 8) * ZSTR + k0 + qc + 8];
#pragma unroll
        for (int nt = 0; nt < 16; nt++) {
            const int n0 = nt * 8;
            uint32_t b0 = *(const uint32_t*)&Wt[(n0 + gr) * ZSTR + k0 + qc];
            uint32_t b1 = *(const uint32_t*)&Wt[(n0 + gr) * ZSTR + k0 + qc + 8];
            asm volatile(
                "mma.sync.aligned.m16n8k16.row.col.f32.bf16.bf16.f32 "
                "{%0,%1,%2,%3}, {%4,%5,%6,%7}, {%8,%9}, {%0,%1,%2,%3};\n"
                : "+f"(acc[nt][0]), "+f"(acc[nt][1]), "+f"(acc[nt][2]), "+f"(acc[nt][3])
                : "r"(a0), "r"(a1), "r"(a2), "r"(a3), "r"(b0), "r"(b1));
        }
    }

    // Epilogue: write bf16 residual (bias folded into g_mb later)
    const int row0 = t0 + r0 + gr;
    const int row1 = row0 + 8;
#pragma unroll
    for (int nt = 0; nt < 16; nt++) {
        const int col = nt * 8 + qc;
        __nv_bfloat16* p0 = g_band + (((size_t)(b * T_ + row0)) * NB_ + n) * 128 + col;
        __nv_bfloat16* p1 = g_band + (((size_t)(b * T_ + row1)) * NB_ + n) * 128 + col;
        *(__nv_bfloat162*)p0 = __float22bfloat162_rn(make_float2(acc[nt][0], acc[nt][1]));
        *(__nv_bfloat162*)p1 = __float22bfloat162_rn(make_float2(acc[nt][2], acc[nt][3]));
    }
}

// ---------------------------------------------------------------------------
// K2: per-frame mask gather + complex multiply + irfft(2048) + Hann window.
// ---------------------------------------------------------------------------
__device__ __forceinline__ float2 cmul(float2 a, float2 b) {
    return make_float2(a.x * b.x - a.y * b.y, a.x * b.y + a.y * b.x);
}

__global__ __launch_bounds__(256) void k_fft(const float* __restrict__ mix)
{
    __shared__ float  bandv[NB_ * O_];    // 2816 floats
    __shared__ float2 X[FREQ_];           // masked spectrum
    __shared__ float2 bufA[N2];
    __shared__ float2 bufB[N2];

    const int frame = blockIdx.x;         // b*T_ + t
    const int b = frame >> 11;
    const int t = frame & 2047;
    const int tid = threadIdx.x;

    // Load band residuals (bf16) for this frame -> fp32 smem
    {
        const __nv_bfloat162* bf =
            (const __nv_bfloat162*)(g_band + (size_t)frame * (NB_ * O_));
        for (int i = tid; i < NB_ * O_ / 2; i += 256) {
            float2 v = __bfloat1622float2(bf[i]);
            bandv[2 * i] = v.x;
            bandv[2 * i + 1] = v.y;
        }
    }
    __syncthreads();

    // Build X[f] = mask[f] * mix[f] (complex); bias+1/cnt from g_mb table
    const float* mr = mix + ((size_t)(b * 2 + 0) * T_ + t) * FREQ_;
    const float* mi = mix + ((size_t)(b * 2 + 1) * T_ + t) * FREQ_;
    for (int f = tid; f < FREQ_; f += 256) {
        float sr = 0.0f, si = 0.0f;
        int n1 = f / 48; if (n1 > 20) n1 = 20;
        int n0 = (f >= 63) ? (f - 63 + 47) / 48 : 0;
        for (int nn = n0; nn <= n1; nn++) {
            int col = f - 48 * nn;
            sr += bandv[nn * 128 + 2 * col];
            si += bandv[nn * 128 + 2 * col + 1];
        }
        if (f >= 961) {
            int col = f - 961;
            sr += bandv[21 * 128 + 2 * col];
            si += bandv[21 * 128 + 2 * col + 1];
        }
        float4 mb = g_mb[f];
        float maskr = fmaf(sr, mb.z, mb.x);
        float maski = fmaf(si, mb.z, mb.y);
        float xr = mr[f], xi = mi[f];
        X[f] = make_float2(maskr * xr - maski * xi, maskr * xi + maski * xr);
    }
    __syncthreads();

    // Hermitian pack (imag of DC/Nyquist discarded, matching C2R semantics)
    for (int j = tid; j < N2; j += 256) {
        float2 zv;
        if (j == 0) {
            float x0 = X[0].x, xn = X[1024].x;
            zv = make_float2(x0 + xn, x0 - xn);
        } else {
            float2 u = X[j];
            float2 v = X[1024 - j];
            float Ar = u.x + v.x, Ai = u.y - v.y;
            float Dr = u.x - v.x, Di = u.y + v.y;
            float2 cs = g_pk[j];            // (cos, sin)
            float c = cs.x, s = cs.y;
            zv = make_float2(Ar - s * Dr - c * Di, Ai + c * Dr - s * Di);
        }
        bufA[j] = zv;
    }
    __syncthreads();

    // 5 radix-4 Stockham stages, inverse (e^{+i}), natural in / natural out
    float2* src = bufA;
    float2* dst = bufB;
#pragma unroll
    for (int stage = 0; stage < 5; stage++) {
        const int shift = 2 * stage;
        const int ns = 1 << shift;
        const int j = tid;                 // N2/4 == blockDim
        const int base = j & (ns - 1);

        float2 a  = src[j];
        float2 bb = src[j + 256];
        float2 cc = src[j + 512];
        float2 dd = src[j + 768];

        float2 w1 = g_tw[stage][j];        // exp(+i*pi*base/(2ns))
        float2 w2 = cmul(w1, w1);
        float2 w3 = cmul(w2, w1);
        bb = cmul(bb, w1);
        cc = cmul(cc, w2);
        dd = cmul(dd, w3);

        float2 p = make_float2(a.x + cc.x, a.y + cc.y);
        float2 m = make_float2(a.x - cc.x, a.y - cc.y);
        float2 q = make_float2(bb.x + dd.x, bb.y + dd.y);
        float2 r = make_float2(bb.x - dd.x, bb.y - dd.y);
        float2 ir = make_float2(-r.y, r.x);   // i * r

        int idx = ((j >> shift) << (shift + 2)) + base;
        dst[idx]          = make_float2(p.x + q.x, p.y + q.y);   // Y0
        dst[idx + ns]     = make_float2(m.x + ir.x, m.y + ir.y); // Y1
        dst[idx + 2 * ns] = make_float2(p.x - q.x, p.y - q.y);   // Y2
        dst[idx + 3 * ns] = make_float2(m.x - ir.x, m.y - ir.y); // Y3
        __syncthreads();
        float2* tmp = src; src = dst; dst = tmp;
    }

    // unpack to 2048 real samples, apply Hann window, 1/2048 irfft scale
    const float invN = 1.0f / 2048.0f;
    float* fout = g_frames + (size_t)frame * NFFT;
#pragma unroll
    for (int rix = 0; rix < 8; rix++) {
        int i = tid + 256 * rix;
        float2 zm = src[i >> 1];
        float v = (i & 1) ? zm.y : zm.x;
        fout[i] = v * invN * g_win[i];
    }
}

// ---------------------------------------------------------------------------
// K3: overlap-add gather, 4 samples/thread (float4), analytic env=1.5 interior
// ---------------------------------------------------------------------------
__global__ __launch_bounds__(128) void k_ola(float* __restrict__ out)
{
    const int b = blockIdx.y;
    const int s0 = (blockIdx.x * 128 + threadIdx.x) * 4;  // 0..OUTL-4 (exact)
    const int p0 = s0 + 1024;                             // p0 % 4 == 0

    int thi = p0 >> 9;
    if (thi > T_ - 1) thi = T_ - 1;
    int tlo = (p0 >= NFFT) ? ((p0 - 1536) >> 9) : 0;
    // 4-sample pack never crosses a hop boundary (p0%512 <= 508), so all 4
    // samples share [tlo, thi] and each frame read is a contiguous float4.

    float4 acc = make_float4(0.f, 0.f, 0.f, 0.f);
    if (thi - tlo == 3) {
        // interior: COLA sum of hann^2 over 4 phases = 1.5 exactly
#pragma unroll
        for (int k = 0; k < 4; k++) {
            int t = tlo + k;
            float4 v = *(const float4*)(g_frames + ((size_t)(b * T_ + t)) * NFFT + (p0 - (t << 9)));
            acc.x += v.x; acc.y += v.y; acc.z += v.z; acc.w += v.w;
        }
        const float inv = 1.0f / 1.5f;
        acc.x *= inv; acc.y *= inv; acc.z *= inv; acc.w *= inv;
    } else {
        float4 env = make_float4(0.f, 0.f, 0.f, 0.f);
        for (int t = tlo; t <= thi; t++) {
            int off = p0 - (t << 9);
            float4 v = *(const float4*)(g_frames + ((size_t)(b * T_ + t)) * NFFT + off);
            float4 w2 = *(const float4*)&g_win2[off];
            acc.x += v.x; acc.y += v.y; acc.z += v.z; acc.w += v.w;
            env.x += w2.x; env.y += w2.y; env.z += w2.z; env.w += w2.w;
        }
        acc.x /= (env.x > 1e-11f ? env.x : 1.0f);
        acc.y /= (env.y > 1e-11f ? env.y : 1.0f);
        acc.z /= (env.z > 1e-11f ? env.z : 1.0f);
        acc.w /= (env.w > 1e-11f ? env.w : 1.0f);
    }
    *(float4*)(out + (size_t)b * OUTL + s0) = acc;
}

// ---------------------------------------------------------------------------
extern "C" void kernel_launch(void* const* d_in, const int* in_sizes, int n_in,
                              void* d_out, int out_size)
{
    const float* z    = (const float*)d_in[0];
    const float* mix  = (const float*)d_in[1];
    const float* W    = (const float*)d_in[2];
    const float* bias = (const float*)d_in[3];
    float* out = (float*)d_out;

    const int smem_gemm = (128 * ZSTR * 2) * 2;   // Za + Wt (bf16)
    cudaFuncSetAttribute(k_gemm, cudaFuncAttributeMaxDynamicSharedMemorySize, smem_gemm);

    k_init<<<8, 256>>>(bias);
    k_gemm<<<dim3(T_ / 128, NB_, B_), 256, smem_gemm>>>(z, W);
    k_fft<<<B_ * T_, 256>>>(mix);
    k_ola<<<dim3(OUTL / 512, B_), 128>>>(out);
}

// round 7
// speedup vs baseline: 2.8473x; 1.2912x over previous
#include <cuda_runtime.h>
#include <cuda_bf16.h>
#include <cstdint>
#include <math.h>

#define B_    8
#define T_    2048
#define NB_   22
#define D_    128
#define O_    128      // WIDTH*2
#define FREQ_ 1025
#define NFFT  2048
#define N2    1024
#define HOP_  512
#define OUTL  1048064  // HOP*(T-1)

// Scratch (static device globals; no runtime allocation)
__device__ __nv_bfloat16 g_band[(size_t)B_ * T_ * NB_ * O_];  // band residual (no bias), bf16
__device__ __nv_bfloat16 g_Wt[(size_t)NB_ * 128 * 128];       // W transposed [n][o][d], bf16
__device__ float g_frames[(size_t)B_ * T_ * NFFT];            // windowed istft frames

// Precomputed tables (filled by k_init every launch; deterministic)
__device__ float2 g_tw[5][256];   // FFT stage twiddles w1
__device__ float2 g_pk[1024];     // hermitian pack twiddles (cos, sin) of pi*j/1024
__device__ float  g_win[2048];    // hann window
__device__ float  g_win2[2048];   // hann^2
__device__ float4 g_mb[FREQ_];    // (bias_r*invw, bias_i*invw, invw, 0) per freq

#define ZSTR 136   // padded bf16 row stride (272 B; 16B-aligned rows, ldmatrix conflict-free)

// ---------------------------------------------------------------------------
// K0: fill twiddle/window/mask-bias tables
// ---------------------------------------------------------------------------
__global__ void k_init(const float* __restrict__ bias)
{
    int i = blockIdx.x * 256 + threadIdx.x;   // 0..2047
    if (i < 2048) {
        float w = 0.5f - 0.5f * cospif((float)i * (1.0f / 1024.0f));
        g_win[i] = w;
        g_win2[i] = w * w;
    }
    if (i < 1024) {
        float s, c;
        sincospif((float)i * (1.0f / 1024.0f), &s, &c);
        g_pk[i] = make_float2(c, s);
    }
    if (i < 256) {
#pragma unroll
        for (int st = 0; st < 5; st++) {
            int ns = 1 << (2 * st);
            int base = i & (ns - 1);
            float s, c;
            sincospif((float)base / (float)(2 * ns), &s, &c);
            g_tw[st][i] = make_float2(c, s);
        }
    }
    if (i < FREQ_) {
        int f = i;
        float br = 0.0f, bi = 0.0f;
        int cnt = 0;
        int n1 = f / 48; if (n1 > 20) n1 = 20;
        int n0 = (f >= 63) ? (f - 63 + 47) / 48 : 0;
        for (int nn = n0; nn <= n1; nn++) {
            int col = f - 48 * nn;
            br += bias[nn * 128 + 2 * col];
            bi += bias[nn * 128 + 2 * col + 1];
            cnt++;
        }
        if (f >= 961) {
            int col = f - 961;
            br += bias[21 * 128 + 2 * col];
            bi += bias[21 * 128 + 2 * col + 1];
            cnt++;
        }
        float invw = 1.0f / (float)(cnt > 0 ? cnt : 1);
        g_mb[f] = make_float4(br * invw, bi * invw, invw, 0.0f);
    }
}

// ---------------------------------------------------------------------------
// K0b: transpose W (fp32 [n][d][o]) -> g_Wt (bf16 [n][o][d]), once per band.
// ---------------------------------------------------------------------------
__global__ __launch_bounds__(256) void k_prep(const float* __restrict__ W)
{
    __shared__ __nv_bfloat16 tile[128 * ZSTR];
    const int n = blockIdx.x;
    const int tid = threadIdx.x;
#pragma unroll
    for (int i = 0; i < 64; i++) {
        int idx = tid + 256 * i;          // 0..16383
        int d = idx >> 7;
        int o = idx & 127;
        tile[o * ZSTR + d] = __float2bfloat16(W[(size_t)n * 16384 + idx]);
    }
    __syncthreads();
#pragma unroll
    for (int i = 0; i < 8; i++) {
        int idx = tid + 256 * i;          // 0..2047 uint4s
        int row = idx >> 4;
        int c = idx & 15;
        *(uint4*)(g_Wt + (size_t)n * 16384 + row * 128 + c * 8) =
            *(const uint4*)&tile[row * ZSTR + c * 8];
    }
}

// ---------------------------------------------------------------------------
// K1: band GEMM via bf16 mma.sync (m16n8k16) + ldmatrix fragment loads.
// Writes bf16 RESIDUAL (no bias).
// ---------------------------------------------------------------------------
__global__ __launch_bounds__(256) void k_gemm(const float* __restrict__ z)
{
    extern __shared__ char smraw[];
    __nv_bfloat16* Za = (__nv_bfloat16*)smraw;            // [128][ZSTR]
    __nv_bfloat16* Wt = Za + 128 * ZSTR;                  // [128][ZSTR]  (o-major: Wt[o][d])

    const int n  = blockIdx.y;
    const int b  = blockIdx.z;
    const int t0 = blockIdx.x * 128;
    const int tid = threadIdx.x;

    // Load z tile 128x128 fp32 -> bf16 smem (row-major)
#pragma unroll
    for (int i = 0; i < 16; i++) {
        int idx = tid + 256 * i;          // 0..4095 float4s
        int r = idx >> 5;
        int c4 = idx & 31;
        float4 v = *(const float4*)(z + (((size_t)(b * T_ + t0 + r)) * NB_ + n) * 128 + c4 * 4);
        __nv_bfloat162* dst = (__nv_bfloat162*)&Za[r * ZSTR + c4 * 4];
        dst[0] = __float22bfloat162_rn(make_float2(v.x, v.y));
        dst[1] = __float22bfloat162_rn(make_float2(v.z, v.w));
    }

    // Copy pre-transposed Wt[n] (bf16, rows of 128) into smem via uint4
#pragma unroll
    for (int i = 0; i < 8; i++) {
        int idx = tid + 256 * i;          // 0..2047 uint4s
        int row = idx >> 4;
        int c = idx & 15;
        *(uint4*)&Wt[row * ZSTR + c * 8] =
            *(const uint4*)(g_Wt + (size_t)n * 16384 + row * 128 + c * 8);
    }
    __syncthreads();

    const int w    = tid >> 5;
    const int lane = tid & 31;
    const int gr   = lane >> 2;         // 0..7
    const int qc   = (lane & 3) * 2;    // 0,2,4,6
    const int r0   = w * 16;

    // ldmatrix lane addresses
    const int l8 = lane & 7;
    const int g  = lane >> 3;           // 0..3
    uint32_t za_s = (uint32_t)__cvta_generic_to_shared(Za);
    uint32_t wt_s = (uint32_t)__cvta_generic_to_shared(Wt);
    // A x4: m0=(rows r0..+7,k0..7) m1=(+8,k0..7) m2=(r0..,k8..15) m3=(+8,k8..15)
    uint32_t aaddr = za_s + (uint32_t)(((r0 + l8 + 8 * (g & 1)) * ZSTR + 8 * (g >> 1)) * 2);
    // B x4 (nt pair): m0=(n0..7,k0..7) m1=(n0..7,k8..15) m2=(n8..15,k0..7) m3=(n8..15,k8..15)
    uint32_t baddr0 = wt_s + (uint32_t)(((l8 + 8 * (g >> 1)) * ZSTR + 8 * (g & 1)) * 2);

    float acc[16][4];
#pragma unroll
    for (int nt = 0; nt < 16; nt++)
#pragma unroll
        for (int j = 0; j < 4; j++) acc[nt][j] = 0.0f;

#pragma unroll
    for (int ks = 0; ks < 8; ks++) {
        const uint32_t koff = ks * 16 * 2;   // bytes
        uint32_t a0, a1, a2, a3;
        asm volatile("ldmatrix.sync.aligned.m8n8.x4.shared.b16 {%0,%1,%2,%3}, [%4];"
                     : "=r"(a0), "=r"(a1), "=r"(a2), "=r"(a3) : "r"(aaddr + koff));
#pragma unroll
        for (int ntp = 0; ntp < 8; ntp++) {
            uint32_t q0, q1, q2, q3;
            uint32_t ba = baddr0 + (uint32_t)(ntp * 16 * ZSTR * 2) + koff;
            asm volatile("ldmatrix.sync.aligned.m8n8.x4.shared.b16 {%0,%1,%2,%3}, [%4];"
                         : "=r"(q0), "=r"(q1), "=r"(q2), "=r"(q3) : "r"(ba));
            asm volatile(
                "mma.sync.aligned.m16n8k16.row.col.f32.bf16.bf16.f32 "
                "{%0,%1,%2,%3}, {%4,%5,%6,%7}, {%8,%9}, {%0,%1,%2,%3};\n"
                : "+f"(acc[2 * ntp][0]), "+f"(acc[2 * ntp][1]),
                  "+f"(acc[2 * ntp][2]), "+f"(acc[2 * ntp][3])
                : "r"(a0), "r"(a1), "r"(a2), "r"(a3), "r"(q0), "r"(q1));
            asm volatile(
                "mma.sync.aligned.m16n8k16.row.col.f32.bf16.bf16.f32 "
                "{%0,%1,%2,%3}, {%4,%5,%6,%7}, {%8,%9}, {%0,%1,%2,%3};\n"
                : "+f"(acc[2 * ntp + 1][0]), "+f"(acc[2 * ntp + 1][1]),
                  "+f"(acc[2 * ntp + 1][2]), "+f"(acc[2 * ntp + 1][3])
                : "r"(a0), "r"(a1), "r"(a2), "r"(a3), "r"(q2), "r"(q3));
        }
    }

    // Epilogue: write bf16 residual (bias folded into g_mb)
    const int row0 = t0 + r0 + gr;
    const int row1 = row0 + 8;
#pragma unroll
    for (int nt = 0; nt < 16; nt++) {
        const int col = nt * 8 + qc;
        __nv_bfloat16* p0 = g_band + (((size_t)(b * T_ + row0)) * NB_ + n) * 128 + col;
        __nv_bfloat16* p1 = g_band + (((size_t)(b * T_ + row1)) * NB_ + n) * 128 + col;
        *(__nv_bfloat162*)p0 = __float22bfloat162_rn(make_float2(acc[nt][0], acc[nt][1]));
        *(__nv_bfloat162*)p1 = __float22bfloat162_rn(make_float2(acc[nt][2], acc[nt][3]));
    }
}

// ---------------------------------------------------------------------------
// K2: per-frame mask gather + complex multiply + irfft(2048) + Hann window.
// Fused mask/mix/hermitian-pack phase (no X[] array), 5 radix-4 smem stages.
// ---------------------------------------------------------------------------
__device__ __forceinline__ float2 cmul(float2 a, float2 b) {
    return make_float2(a.x * b.x - a.y * b.y, a.x * b.y + a.y * b.x);
}

__global__ __launch_bounds__(256) void k_fft(const float* __restrict__ mix)
{
    __shared__ float  bandv[NB_ * O_];    // 2816 floats
    __shared__ float2 bufA[N2];
    __shared__ float2 bufB[N2];

    const int frame = blockIdx.x;         // b*T_ + t
    const int b = frame >> 11;
    const int t = frame & 2047;
    const int tid = threadIdx.x;

    // Load band residuals (bf16) for this frame -> fp32 smem
    {
        const __nv_bfloat162* bf =
            (const __nv_bfloat162*)(g_band + (size_t)frame * (NB_ * O_));
        for (int i = tid; i < NB_ * O_ / 2; i += 256) {
            float2 v = __bfloat1622float2(bf[i]);
            bandv[2 * i] = v.x;
            bandv[2 * i + 1] = v.y;
        }
    }
    __syncthreads();

    const float* mr = mix + ((size_t)(b * 2 + 0) * T_ + t) * FREQ_;
    const float* mi = mix + ((size_t)(b * 2 + 1) * T_ + t) * FREQ_;

    // X(f) = (residual-mask(f) + bias-mask(f)) * mix(f)
    auto computeX = [&](int f) -> float2 {
        float sr = 0.0f, si = 0.0f;
        int n1 = f / 48; if (n1 > 20) n1 = 20;
        int n0 = (f >= 63) ? (f - 63 + 47) / 48 : 0;
        for (int nn = n0; nn <= n1; nn++) {
            int col = f - 48 * nn;
            sr += bandv[nn * 128 + 2 * col];
            si += bandv[nn * 128 + 2 * col + 1];
        }
        if (f >= 961) {
            int col = f - 961;
            sr += bandv[21 * 128 + 2 * col];
            si += bandv[21 * 128 + 2 * col + 1];
        }
        float4 mb = g_mb[f];
        float maskr = fmaf(sr, mb.z, mb.x);
        float maski = fmaf(si, mb.z, mb.y);
        float xr = mr[f], xi = mi[f];
        return make_float2(maskr * xr - maski * xi, maskr * xi + maski * xr);
    };

    // Fused hermitian pack: pair (j, 1024-j) shares (Ar,Ai,Dr,Di,c,s)
    auto packPair = [&](int j) {
        float2 u = computeX(j);
        float2 v = computeX(1024 - j);
        float Ar = u.x + v.x, Ai = u.y - v.y;
        float Dr = u.x - v.x, Di = u.y + v.y;
        float2 cs = g_pk[j];
        float c = cs.x, s = cs.y;
        bufA[j]        = make_float2(Ar - s * Dr - c * Di,  Ai + c * Dr - s * Di);
        bufA[1024 - j] = make_float2(Ar + s * Dr + c * Di, -Ai + c * Dr - s * Di);
    };

    packPair(tid + 256);                  // j in 256..511, partner 513..768
    if (tid == 0) {
        float x0 = computeX(0).x;
        float xn = computeX(1024).x;
        bufA[0] = make_float2(x0 + xn, x0 - xn);
        float2 u = computeX(512);
        bufA[512] = make_float2(2.0f * u.x, -2.0f * u.y);
    } else {
        packPair(tid);                    // j in 1..255, partner 769..1023
    }
    __syncthreads();

    // 5 radix-4 Stockham stages, inverse (e^{+i}), natural in / natural out
    float2* src = bufA;
    float2* dst = bufB;
#pragma unroll
    for (int stage = 0; stage < 5; stage++) {
        const int shift = 2 * stage;
        const int ns = 1 << shift;
        const int j = tid;
        const int base = j & (ns - 1);

        float2 a  = src[j];
        float2 bb = src[j + 256];
        float2 cc = src[j + 512];
        float2 dd = src[j + 768];

        float2 w1 = g_tw[stage][j];
        float2 w2 = cmul(w1, w1);
        float2 w3 = cmul(w2, w1);
        bb = cmul(bb, w1);
        cc = cmul(cc, w2);
        dd = cmul(dd, w3);

        float2 p = make_float2(a.x + cc.x, a.y + cc.y);
        float2 m = make_float2(a.x - cc.x, a.y - cc.y);
        float2 q = make_float2(bb.x + dd.x, bb.y + dd.y);
        float2 r = make_float2(bb.x - dd.x, bb.y - dd.y);
        float2 ir = make_float2(-r.y, r.x);

        int idx = ((j >> shift) << (shift + 2)) + base;
        dst[idx]          = make_float2(p.x + q.x, p.y + q.y);
        dst[idx + ns]     = make_float2(m.x + ir.x, m.y + ir.y);
        dst[idx + 2 * ns] = make_float2(p.x - q.x, p.y - q.y);
        dst[idx + 3 * ns] = make_float2(m.x - ir.x, m.y - ir.y);
        __syncthreads();
        float2* tmp = src; src = dst; dst = tmp;
    }

    // unpack to 2048 real samples, apply Hann window, 1/2048 irfft scale
    const float invN = 1.0f / 2048.0f;
    float* fout = g_frames + (size_t)frame * NFFT;
#pragma unroll
    for (int rix = 0; rix < 8; rix++) {
        int i = tid + 256 * rix;
        float2 zm = src[i >> 1];
        float v = (i & 1) ? zm.y : zm.x;
        fout[i] = v * invN * g_win[i];
    }
}

// ---------------------------------------------------------------------------
// K3: overlap-add gather, 4 samples/thread (float4), analytic env=1.5 interior
// ---------------------------------------------------------------------------
__global__ __launch_bounds__(128) void k_ola(float* __restrict__ out)
{
    const int b = blockIdx.y;
    const int s0 = (blockIdx.x * 128 + threadIdx.x) * 4;
    const int p0 = s0 + 1024;

    int thi = p0 >> 9;
    if (thi > T_ - 1) thi = T_ - 1;
    int tlo = (p0 >= NFFT) ? ((p0 - 1536) >> 9) : 0;

    float4 acc = make_float4(0.f, 0.f, 0.f, 0.f);
    if (thi - tlo == 3) {
#pragma unroll
        for (int k = 0; k < 4; k++) {
            int t = tlo + k;
            float4 v = *(const float4*)(g_frames + ((size_t)(b * T_ + t)) * NFFT + (p0 - (t << 9)));
            acc.x += v.x; acc.y += v.y; acc.z += v.z; acc.w += v.w;
        }
        const float inv = 1.0f / 1.5f;
        acc.x *= inv; acc.y *= inv; acc.z *= inv; acc.w *= inv;
    } else {
        float4 env = make_float4(0.f, 0.f, 0.f, 0.f);
        for (int t = tlo; t <= thi; t++) {
            int off = p0 - (t << 9);
            float4 v = *(const float4*)(g_frames + ((size_t)(b * T_ + t)) * NFFT + off);
            float4 w2 = *(const float4*)&g_win2[off];
            acc.x += v.x; acc.y += v.y; acc.z += v.z; acc.w += v.w;
            env.x += w2.x; env.y += w2.y; env.z += w2.z; env.w += w2.w;
        }
        acc.x /= (env.x > 1e-11f ? env.x : 1.0f);
        acc.y /= (env.y > 1e-11f ? env.y : 1.0f);
        acc.z /= (env.z > 1e-11f ? env.z : 1.0f);
        acc.w /= (env.w > 1e-11f ? env.w : 1.0f);
    }
    *(float4*)(out + (size_t)b * OUTL + s0) = acc;
}

// ---------------------------------------------------------------------------
extern "C" void kernel_launch(void* const* d_in, const int* in_sizes, int n_in,
                              void* d_out, int out_size)
{
    const float* z    = (const float*)d_in[0];
    const float* mix  = (const float*)d_in[1];
    const float* W    = (const float*)d_in[2];
    const float* bias = (const float*)d_in[3];
    float* out = (float*)d_out;

    const int smem_gemm = (128 * ZSTR * 2) * 2;   // Za + Wt (bf16)
    cudaFuncSetAttribute(k_gemm, cudaFuncAttributeMaxDynamicSharedMemorySize, smem_gemm);

    k_init<<<8, 256>>>(bias);
    k_prep<<<NB_, 256>>>(W);
    k_gemm<<<dim3(T_ / 128, NB_, B_), 256, smem_gemm>>>(z);
    k_fft<<<B_ * T_, 256>>>(mix);
    k_ola<<<dim3(OUTL / 512, B_), 128>>>(out);
}

// round 9
// speedup vs baseline: 3.4409x; 1.2085x over previous
#include <cuda_runtime.h>
#include <cuda_bf16.h>
#include <cstdint>
#include <math.h>

#define B_    8
#define T_    2048
#define NB_   22
#define D_    128
#define O_    128      // WIDTH*2
#define FREQ_ 1025
#define NFFT  2048
#define N2    1024
#define HOP_  512
#define OUTL  1048064  // HOP*(T-1)

// Scratch (static device globals; no runtime allocation)
__device__ __nv_bfloat16 g_band[(size_t)B_ * T_ * NB_ * O_];  // band residual (no bias), bf16
__device__ __nv_bfloat16 g_Wt[(size_t)NB_ * 128 * 128];       // W transposed [n][o][d], bf16
__device__ float g_frames[(size_t)B_ * T_ * NFFT];            // windowed istft frames

// Precomputed tables (filled by k_init every launch; deterministic)
__device__ float2 g_tw[5][256];   // FFT stage twiddles w1
__device__ float2 g_pk[1024];     // hermitian pack twiddles (cos, sin) of pi*j/1024
__device__ float  g_win2[2048];   // hann^2
__device__ float2 g_winp[1024];   // (win[2m], win[2m+1]) * (1/2048)
__device__ float4 g_mb[FREQ_];    // (bias_r*invw, bias_i*invw, invw, 0) per freq

#define ZSTR 136   // padded bf16 row stride

// ---------------------------------------------------------------------------
// K0: fill twiddle/window/mask-bias tables
// ---------------------------------------------------------------------------
__global__ void k_init(const float* __restrict__ bias)
{
    int i = blockIdx.x * 256 + threadIdx.x;   // 0..2047
    if (i < 2048) {
        float w = 0.5f - 0.5f * cospif((float)i * (1.0f / 1024.0f));
        g_win2[i] = w * w;
    }
    if (i < 1024) {
        float s, c;
        sincospif((float)i * (1.0f / 1024.0f), &s, &c);
        g_pk[i] = make_float2(c, s);
        const float invN = 1.0f / 2048.0f;
        float w0 = 0.5f - 0.5f * cospif((float)(2 * i) * (1.0f / 1024.0f));
        float w1 = 0.5f - 0.5f * cospif((float)(2 * i + 1) * (1.0f / 1024.0f));
        g_winp[i] = make_float2(w0 * invN, w1 * invN);
    }
    if (i < 256) {
#pragma unroll
        for (int st = 0; st < 5; st++) {
            int ns = 1 << (2 * st);
            int base = i & (ns - 1);
            float s, c;
            sincospif((float)base / (float)(2 * ns), &s, &c);
            g_tw[st][i] = make_float2(c, s);
        }
    }
    if (i < FREQ_) {
        int f = i;
        float br = 0.0f, bi = 0.0f;
        int cnt = 0;
        int n1 = f / 48; if (n1 > 20) n1 = 20;
        int n0 = (f >= 63) ? (f - 63 + 47) / 48 : 0;
        for (int nn = n0; nn <= n1; nn++) {
            int col = f - 48 * nn;
            br += bias[nn * 128 + 2 * col];
            bi += bias[nn * 128 + 2 * col + 1];
            cnt++;
        }
        if (f >= 961) {
            int col = f - 961;
            br += bias[21 * 128 + 2 * col];
            bi += bias[21 * 128 + 2 * col + 1];
            cnt++;
        }
        float invw = 1.0f / (float)(cnt > 0 ? cnt : 1);
        g_mb[f] = make_float4(br * invw, bi * invw, invw, 0.0f);
    }
}

// ---------------------------------------------------------------------------
// K0b: transpose W (fp32 [n][d][o]) -> g_Wt (bf16 [n][o][d]), once per band.
// ---------------------------------------------------------------------------
__global__ __launch_bounds__(256) void k_prep(const float* __restrict__ W)
{
    __shared__ __nv_bfloat16 tile[128 * ZSTR];
    const int n = blockIdx.x;
    const int tid = threadIdx.x;
#pragma unroll
    for (int i = 0; i < 64; i++) {
        int idx = tid + 256 * i;          // 0..16383
        int d = idx >> 7;
        int o = idx & 127;
        tile[o * ZSTR + d] = __float2bfloat16(W[(size_t)n * 16384 + idx]);
    }
    __syncthreads();
#pragma unroll
    for (int i = 0; i < 8; i++) {
        int idx = tid + 256 * i;          // 0..2047 uint4s
        int row = idx >> 4;
        int c = idx & 15;
        *(uint4*)(g_Wt + (size_t)n * 16384 + row * 128 + c * 8) =
            *(const uint4*)&tile[row * ZSTR + c * 8];
    }
}

// ---------------------------------------------------------------------------
// K1: band GEMM via bf16 mma.sync (m16n8k16) + ldmatrix fragment loads.
// Writes bf16 RESIDUAL (no bias).
// ---------------------------------------------------------------------------
__global__ __launch_bounds__(256) void k_gemm(const float* __restrict__ z)
{
    extern __shared__ char smraw[];
    __nv_bfloat16* Za = (__nv_bfloat16*)smraw;            // [128][ZSTR]
    __nv_bfloat16* Wt = Za + 128 * ZSTR;                  // [128][ZSTR]  (o-major)

    const int n  = blockIdx.y;
    const int b  = blockIdx.z;
    const int t0 = blockIdx.x * 128;
    const int tid = threadIdx.x;

#pragma unroll
    for (int i = 0; i < 16; i++) {
        int idx = tid + 256 * i;          // 0..4095 float4s
        int r = idx >> 5;
        int c4 = idx & 31;
        float4 v = *(const float4*)(z + (((size_t)(b * T_ + t0 + r)) * NB_ + n) * 128 + c4 * 4);
        __nv_bfloat162* dst = (__nv_bfloat162*)&Za[r * ZSTR + c4 * 4];
        dst[0] = __float22bfloat162_rn(make_float2(v.x, v.y));
        dst[1] = __float22bfloat162_rn(make_float2(v.z, v.w));
    }

#pragma unroll
    for (int i = 0; i < 8; i++) {
        int idx = tid + 256 * i;          // 0..2047 uint4s
        int row = idx >> 4;
        int c = idx & 15;
        *(uint4*)&Wt[row * ZSTR + c * 8] =
            *(const uint4*)(g_Wt + (size_t)n * 16384 + row * 128 + c * 8);
    }
    __syncthreads();

    const int w    = tid >> 5;
    const int lane = tid & 31;
    const int gr   = lane >> 2;
    const int qc   = (lane & 3) * 2;
    const int r0   = w * 16;

    const int l8 = lane & 7;
    const int g  = lane >> 3;
    uint32_t za_s = (uint32_t)__cvta_generic_to_shared(Za);
    uint32_t wt_s = (uint32_t)__cvta_generic_to_shared(Wt);
    uint32_t aaddr = za_s + (uint32_t)(((r0 + l8 + 8 * (g & 1)) * ZSTR + 8 * (g >> 1)) * 2);
    uint32_t baddr0 = wt_s + (uint32_t)(((l8 + 8 * (g >> 1)) * ZSTR + 8 * (g & 1)) * 2);

    float acc[16][4];
#pragma unroll
    for (int nt = 0; nt < 16; nt++)
#pragma unroll
        for (int j = 0; j < 4; j++) acc[nt][j] = 0.0f;

#pragma unroll
    for (int ks = 0; ks < 8; ks++) {
        const uint32_t koff = ks * 16 * 2;
        uint32_t a0, a1, a2, a3;
        asm volatile("ldmatrix.sync.aligned.m8n8.x4.shared.b16 {%0,%1,%2,%3}, [%4];"
                     : "=r"(a0), "=r"(a1), "=r"(a2), "=r"(a3) : "r"(aaddr + koff));
#pragma unroll
        for (int ntp = 0; ntp < 8; ntp++) {
            uint32_t q0, q1, q2, q3;
            uint32_t ba = baddr0 + (uint32_t)(ntp * 16 * ZSTR * 2) + koff;
            asm volatile("ldmatrix.sync.aligned.m8n8.x4.shared.b16 {%0,%1,%2,%3}, [%4];"
                         : "=r"(q0), "=r"(q1), "=r"(q2), "=r"(q3) : "r"(ba));
            asm volatile(
                "mma.sync.aligned.m16n8k16.row.col.f32.bf16.bf16.f32 "
                "{%0,%1,%2,%3}, {%4,%5,%6,%7}, {%8,%9}, {%0,%1,%2,%3};\n"
                : "+f"(acc[2 * ntp][0]), "+f"(acc[2 * ntp][1]),
                  "+f"(acc[2 * ntp][2]), "+f"(acc[2 * ntp][3])
                : "r"(a0), "r"(a1), "r"(a2), "r"(a3), "r"(q0), "r"(q1));
            asm volatile(
                "mma.sync.aligned.m16n8k16.row.col.f32.bf16.bf16.f32 "
                "{%0,%1,%2,%3}, {%4,%5,%6,%7}, {%8,%9}, {%0,%1,%2,%3};\n"
                : "+f"(acc[2 * ntp + 1][0]), "+f"(acc[2 * ntp + 1][1]),
                  "+f"(acc[2 * ntp + 1][2]), "+f"(acc[2 * ntp + 1][3])
                : "r"(a0), "r"(a1), "r"(a2), "r"(a3), "r"(q2), "r"(q3));
        }
    }

    const int row0 = t0 + r0 + gr;
    const int row1 = row0 + 8;
#pragma unroll
    for (int nt = 0; nt < 16; nt++) {
        const int col = nt * 8 + qc;
        __nv_bfloat16* p0 = g_band + (((size_t)(b * T_ + row0)) * NB_ + n) * 128 + col;
        __nv_bfloat16* p1 = g_band + (((size_t)(b * T_ + row1)) * NB_ + n) * 128 + col;
        *(__nv_bfloat162*)p0 = __float22bfloat162_rn(make_float2(acc[nt][0], acc[nt][1]));
        *(__nv_bfloat162*)p1 = __float22bfloat162_rn(make_float2(acc[nt][2], acc[nt][3]));
    }
}

// ---------------------------------------------------------------------------
// K2: mask gather (bf16 smem) + complex mult + irfft(2048) + window.
// 5 radix-4 stages; stage 4 is in-place -> writes windowed output straight
// from registers to global (no final smem round-trip).
// ---------------------------------------------------------------------------
__device__ __forceinline__ float2 cmul(float2 a, float2 b) {
    return make_float2(a.x * b.x - a.y * b.y, a.x * b.y + a.y * b.x);
}

__global__ __launch_bounds__(256) void k_fft(const float* __restrict__ mix)
{
    __shared__ __nv_bfloat162 bandv[NB_ * 64];   // 1408 pairs (5.5 KB)
    __shared__ float2 bufA[N2];
    __shared__ float2 bufB[N2];

    const int frame = blockIdx.x;         // b*T_ + t
    const int b = frame >> 11;
    const int t = frame & 2047;
    const int tid = threadIdx.x;

    // Load band residuals (bf16) straight into smem via uint4 (352 of them)
    {
        const uint4* src4 = (const uint4*)(g_band + (size_t)frame * (NB_ * O_));
        uint4* dst4 = (uint4*)bandv;
        if (tid < 176) {
            dst4[tid] = src4[tid];
            dst4[tid + 176] = src4[tid + 176];
        }
    }
    __syncthreads();

    const float* mr = mix + ((size_t)(b * 2 + 0) * T_ + t) * FREQ_;
    const float* mi = mix + ((size_t)(b * 2 + 1) * T_ + t) * FREQ_;

    auto computeX = [&](int f) -> float2 {
        float sr = 0.0f, si = 0.0f;
        int n1 = f / 48; if (n1 > 20) n1 = 20;
        int n0 = (f >= 63) ? (f - 63 + 47) / 48 : 0;
        for (int nn = n0; nn <= n1; nn++) {
            int col = f - 48 * nn;
            float2 v = __bfloat1622float2(bandv[nn * 64 + col]);
            sr += v.x; si += v.y;
        }
        if (f >= 961) {
            float2 v = __bfloat1622float2(bandv[21 * 64 + (f - 961)]);
            sr += v.x; si += v.y;
        }
        float4 mb = g_mb[f];
        float maskr = fmaf(sr, mb.z, mb.x);
        float maski = fmaf(si, mb.z, mb.y);
        float xr = mr[f], xi = mi[f];
        return make_float2(maskr * xr - maski * xi, maskr * xi + maski * xr);
    };

    auto packPair = [&](int j) {
        float2 u = computeX(j);
        float2 v = computeX(1024 - j);
        float Ar = u.x + v.x, Ai = u.y - v.y;
        float Dr = u.x - v.x, Di = u.y + v.y;
        float2 cs = g_pk[j];
        float c = cs.x, s = cs.y;
        bufA[j]        = make_float2(Ar - s * Dr - c * Di,  Ai + c * Dr - s * Di);
        bufA[1024 - j] = make_float2(Ar + s * Dr + c * Di, -Ai + c * Dr - s * Di);
    };

    packPair(tid + 256);
    if (tid == 0) {
        float x0 = computeX(0).x;
        float xn = computeX(1024).x;
        bufA[0] = make_float2(x0 + xn, x0 - xn);
        float2 u = computeX(512);
        bufA[512] = make_float2(2.0f * u.x, -2.0f * u.y);
    } else {
        packPair(tid);
    }
    __syncthreads();

    // Stages 0..3: smem ping-pong (pack->A, s0 A->B, s1 B->A, s2 A->B, s3 B->A)
    float2* src = bufA;
    float2* dst = bufB;
#pragma unroll
    for (int stage = 0; stage < 4; stage++) {
        const int shift = 2 * stage;
        const int ns = 1 << shift;
        const int j = tid;
        const int base = j & (ns - 1);

        float2 a  = src[j];
        float2 bb = src[j + 256];
        float2 cc = src[j + 512];
        float2 dd = src[j + 768];

        float2 w1 = g_tw[stage][j];
        float2 w2 = cmul(w1, w1);
        float2 w3 = cmul(w2, w1);
        bb = cmul(bb, w1);
        cc = cmul(cc, w2);
        dd = cmul(dd, w3);

        float2 p = make_float2(a.x + cc.x, a.y + cc.y);
        float2 m = make_float2(a.x - cc.x, a.y - cc.y);
        float2 q = make_float2(bb.x + dd.x, bb.y + dd.y);
        float2 r = make_float2(bb.x - dd.x, bb.y - dd.y);
        float2 ir = make_float2(-r.y, r.x);

        int idx = ((j >> shift) << (shift + 2)) + base;
        dst[idx]          = make_float2(p.x + q.x, p.y + q.y);
        dst[idx + ns]     = make_float2(m.x + ir.x, m.y + ir.y);
        dst[idx + 2 * ns] = make_float2(p.x - q.x, p.y - q.y);
        dst[idx + 3 * ns] = make_float2(m.x - ir.x, m.y - ir.y);
        __syncthreads();
        float2* tmp = src; src = dst; dst = tmp;
    }

    // Stage 4 (shift=8): in-place positions -> keep results in registers and
    // write windowed real samples directly to global.
    {
        const int j = tid;
        float2 a  = src[j];
        float2 bb = src[j + 256];
        float2 cc = src[j + 512];
        float2 dd = src[j + 768];

        float2 w1 = g_tw[4][j];
        float2 w2 = cmul(w1, w1);
        float2 w3 = cmul(w2, w1);
        bb = cmul(bb, w1);
        cc = cmul(cc, w2);
        dd = cmul(dd, w3);

        float2 p = make_float2(a.x + cc.x, a.y + cc.y);
        float2 m = make_float2(a.x - cc.x, a.y - cc.y);
        float2 q = make_float2(bb.x + dd.x, bb.y + dd.y);
        float2 r = make_float2(bb.x - dd.x, bb.y - dd.y);
        float2 ir = make_float2(-r.y, r.x);

        float2 Y0 = make_float2(p.x + q.x, p.y + q.y);    // -> real[2j], real[2j+1]
        float2 Y1 = make_float2(m.x + ir.x, m.y + ir.y);  // -> at j+256
        float2 Y2 = make_float2(p.x - q.x, p.y - q.y);    // -> at j+512
        float2 Y3 = make_float2(m.x - ir.x, m.y - ir.y);  // -> at j+768

        float2* fo = (float2*)(g_frames + (size_t)frame * NFFT);
        float2 w0t = g_winp[j];
        float2 w1t = g_winp[j + 256];
        float2 w2t = g_winp[j + 512];
        float2 w3t = g_winp[j + 768];
        fo[j]       = make_float2(Y0.x * w0t.x, Y0.y * w0t.y);
        fo[j + 256] = make_float2(Y1.x * w1t.x, Y1.y * w1t.y);
        fo[j + 512] = make_float2(Y2.x * w2t.x, Y2.y * w2t.y);
        fo[j + 768] = make_float2(Y3.x * w3t.x, Y3.y * w3t.y);
    }
}

// ---------------------------------------------------------------------------
// K3: overlap-add gather, 4 samples/thread (float4), analytic env=1.5 interior
// ---------------------------------------------------------------------------
__global__ __launch_bounds__(128) void k_ola(float* __restrict__ out)
{
    const int b = blockIdx.y;
    const int s0 = (blockIdx.x * 128 + threadIdx.x) * 4;
    const int p0 = s0 + 1024;

    int thi = p0 >> 9;
    if (thi > T_ - 1) thi = T_ - 1;
    int tlo = (p0 >= NFFT) ? ((p0 - 1536) >> 9) : 0;

    float4 acc = make_float4(0.f, 0.f, 0.f, 0.f);
    if (thi - tlo == 3) {
#pragma unroll
        for (int k = 0; k < 4; k++) {
            int t = tlo + k;
            float4 v = *(const float4*)(g_frames + ((size_t)(b * T_ + t)) * NFFT + (p0 - (t << 9)));
            acc.x += v.x; acc.y += v.y; acc.z += v.z; acc.w += v.w;
        }
        const float inv = 1.0f / 1.5f;
        acc.x *= inv; acc.y *= inv; acc.z *= inv; acc.w *= inv;
    } else {
        float4 env = make_float4(0.f, 0.f, 0.f, 0.f);
        for (int t = tlo; t <= thi; t++) {
            int off = p0 - (t << 9);
            float4 v = *(const float4*)(g_frames + ((size_t)(b * T_ + t)) * NFFT + off);
            float4 w2 = *(const float4*)&g_win2[off];
            acc.x += v.x; acc.y += v.y; acc.z += v.z; acc.w += v.w;
            env.x += w2.x; env.y += w2.y; env.z += w2.z; env.w += w2.w;
        }
        acc.x /= (env.x > 1e-11f ? env.x : 1.0f);
        acc.y /= (env.y > 1e-11f ? env.y : 1.0f);
        acc.z /= (env.z > 1e-11f ? env.z : 1.0f);
        acc.w /= (env.w > 1e-11f ? env.w : 1.0f);
    }
    *(float4*)(out + (size_t)b * OUTL + s0) = acc;
}

// ---------------------------------------------------------------------------
extern "C" void kernel_launch(void* const* d_in, const int* in_sizes, int n_in,
                              void* d_out, int out_size)
{
    const float* z    = (const float*)d_in[0];
    const float* mix  = (const float*)d_in[1];
    const float* W    = (const float*)d_in[2];
    const float* bias = (const float*)d_in[3];
    float* out = (float*)d_out;

    const int smem_gemm = (128 * ZSTR * 2) * 2;   // Za + Wt (bf16)
    cudaFuncSetAttribute(k_gemm, cudaFuncAttributeMaxDynamicSharedMemorySize, smem_gemm);

    k_init<<<8, 256>>>(bias);
    k_prep<<<NB_, 256>>>(W);
    k_gemm<<<dim3(T_ / 128, NB_, B_), 256, smem_gemm>>>(z);
    k_fft<<<B_ * T_, 256>>>(mix);
    k_ola<<<dim3(OUTL / 512, B_), 128>>>(out);
}